// round 10
// baseline (speedup 1.0000x reference)
#include <cuda_runtime.h>
#include <cuda_bf16.h>
#include <cstdint>

#define NB 8192
#define ND 1024
#define NC 256
#define MARGIN 0.2f
#define THRESH 0.5f
#define NWORD (NB / 32)

#define BM 128
#define BN 128
#define BK 64
#define STAGES 3
#define STAGE_BYTES 32768          // A tile 16 KB + B tile 16 KB
#define B_OFF 16384
#define NSTRIP (NB / BM)           // 64 row strips
#define SWZ(o) ((o) ^ (((o) >> 3) & 0x70))   // SW128 swizzle

// ---------------- device scratch ----------------
__device__ __align__(16) __nv_bfloat16 g_imgh[(size_t)NB * ND];
__device__ __align__(16) __nv_bfloat16 g_txth[(size_t)NB * ND];
__device__ __align__(16) __nv_bfloat16 g_labh[(size_t)NB * NC];
__device__ __align__(16) __nv_bfloat16 g_sim[(size_t)NB * NB];   // 128 MB
__device__ unsigned g_posbits[(size_t)NB * NWORD];               // fully overwritten each run
__device__ unsigned g_rowmax[NB];
__device__ unsigned g_rowflags[NB];
__device__ unsigned g_rowdone[NSTRIP];
__device__ double   g_sum;
__device__ unsigned g_cnt;
__device__ unsigned g_done;

// monotone encode/decode: unsigned atomicMax == float max
__device__ __forceinline__ unsigned encf(float f) {
    unsigned u = __float_as_uint(f);
    return (u & 0x80000000u) ? ~u : (u | 0x80000000u);
}
__device__ __forceinline__ float decf(unsigned u) {
    u = (u & 0x80000000u) ? (u & 0x7fffffffu) : ~u;
    return __uint_as_float(u);
}
__device__ __forceinline__ uint32_t smem_u32(const void* p) {
    uint32_t a;
    asm("{ .reg .u64 t; cvta.to.shared.u64 t, %1; cvt.u32.u64 %0, t; }" : "=r"(a) : "l"(p));
    return a;
}
__device__ __forceinline__ void cp16(uint32_t dst, const void* src) {
    asm volatile("cp.async.cg.shared.global [%0], [%1], 16;" :: "r"(dst), "l"(src));
}
#define CP_COMMIT() asm volatile("cp.async.commit_group;" ::: "memory")
#define CP_WAIT(n)  asm volatile("cp.async.wait_group %0;" :: "n"(n) : "memory")

__device__ __forceinline__ void ldsm4(uint32_t addr, uint32_t r[4]) {
    asm volatile("ldmatrix.sync.aligned.m8n8.x4.shared.b16 {%0,%1,%2,%3}, [%4];"
                 : "=r"(r[0]), "=r"(r[1]), "=r"(r[2]), "=r"(r[3]) : "r"(addr));
}
__device__ __forceinline__ void mma16816(float d[4], const uint32_t a[4],
                                         uint32_t b0, uint32_t b1) {
    asm volatile("mma.sync.aligned.m16n8k16.row.col.f32.bf16.bf16.f32 "
                 "{%0,%1,%2,%3}, {%4,%5,%6,%7}, {%8,%9}, {%0,%1,%2,%3};"
                 : "+f"(d[0]), "+f"(d[1]), "+f"(d[2]), "+f"(d[3])
                 : "r"(a[0]), "r"(a[1]), "r"(a[2]), "r"(a[3]), "r"(b0), "r"(b1));
}

// ---------------- stage load: A[128x64] + B[128x64] bf16, SW128 swizzled ----------------
__device__ __forceinline__ void load_stage(const __nv_bfloat16* __restrict__ Ag,
                                           const __nv_bfloat16* __restrict__ Bg,
                                           int K, int ti, int tj, int k0,
                                           uint32_t sbase, int tid) {
#pragma unroll
    for (int u = 0; u < 4; u++) {
        int ch = u * 256 + tid, row = ch >> 3, cc = ch & 7;
        cp16(sbase + SWZ((uint32_t)(row * 128 + cc * 16)),
             (const char*)(Ag + (size_t)(ti + row) * K + k0) + cc * 16);
    }
#pragma unroll
    for (int u = 0; u < 4; u++) {
        int ch = u * 256 + tid, row = ch >> 3, cc = ch & 7;
        cp16(sbase + B_OFF + SWZ((uint32_t)(row * 128 + cc * 16)),
             (const char*)(Bg + (size_t)(tj + row) * K + k0) + cc * 16);
    }
}

// ---------------- compute one 64-wide K stage: warp tile 32x64, 2x8 mma grid ----------
// Fragment double-buffered; per-kk ldsm address = base ^ (kk*32) (SW128 row-only XOR).
__device__ __forceinline__ void compute_stage(uint32_t sA, uint32_t sB, int lane,
                                              int wy, int wx, float acc[2][8][4]) {
    uint32_t aB[2], bB[4];
#pragma unroll
    for (int mt = 0; mt < 2; mt++) {
        uint32_t row = wy * 32 + mt * 16 + (lane & 15);
        uint32_t t   = (row & 7) * 16;
        uint32_t sel = (lane >> 4) * 16;
        aB[mt] = sA + row * 128 + (sel ^ t);
    }
#pragma unroll
    for (int p = 0; p < 4; p++) {
        uint32_t n   = wx * 64 + p * 16 + (lane >> 4) * 8 + (lane & 7);
        uint32_t t   = (n & 7) * 16;
        uint32_t sel = ((lane >> 3) & 1) * 16;
        bB[p] = sB + n * 128 + (sel ^ t);
    }

    uint32_t af[2][2][4], bf[2][4][4];
    ldsm4(aB[0], af[0][0]); ldsm4(aB[1], af[0][1]);
    ldsm4(bB[0], bf[0][0]); ldsm4(bB[1], bf[0][1]);
    ldsm4(bB[2], bf[0][2]); ldsm4(bB[3], bf[0][3]);

#pragma unroll
    for (int kk = 0; kk < 4; kk++) {
        const int cur = kk & 1, nxt = cur ^ 1;
        if (kk < 3) {
            uint32_t kx = (uint32_t)(kk + 1) * 32;
            ldsm4(aB[0] ^ kx, af[nxt][0]); ldsm4(aB[1] ^ kx, af[nxt][1]);
            ldsm4(bB[0] ^ kx, bf[nxt][0]); ldsm4(bB[1] ^ kx, bf[nxt][1]);
            ldsm4(bB[2] ^ kx, bf[nxt][2]); ldsm4(bB[3] ^ kx, bf[nxt][3]);
        }
#pragma unroll
        for (int mt = 0; mt < 2; mt++)
#pragma unroll
            for (int p = 0; p < 4; p++) {
                mma16816(acc[mt][2 * p],     af[cur][mt], bf[cur][p][0], bf[cur][p][1]);
                mma16816(acc[mt][2 * p + 1], af[cur][mt], bf[cur][p][2], bf[cur][p][3]);
            }
    }
}

// ---------------- pipelined GEMM: acc += A[ti:,:] @ B[tj:,:]^T over K ----------------
template <int K>
__device__ __forceinline__ void gemm(const __nv_bfloat16* __restrict__ Ag,
                                     const __nv_bfloat16* __restrict__ Bg,
                                     int ti, int tj, uint32_t su,
                                     int tid, int lane, int wy, int wx,
                                     float acc[2][8][4]) {
    constexpr int NS = K / BK;
#pragma unroll
    for (int s = 0; s < STAGES - 1; s++) {
        load_stage(Ag, Bg, K, ti, tj, s * BK, su + s * STAGE_BYTES, tid);
        CP_COMMIT();
    }
#pragma unroll 1
    for (int ks = 0; ks < NS; ks++) {
        CP_WAIT(STAGES - 2);
        __syncthreads();
        int nx = ks + STAGES - 1;
        if (nx < NS)
            load_stage(Ag, Bg, K, ti, tj, nx * BK, su + (nx % STAGES) * STAGE_BYTES, tid);
        CP_COMMIT();
        uint32_t sb = su + (ks % STAGES) * STAGE_BYTES;
        compute_stage(sb, sb + B_OFF, lane, wy, wx, acc);
    }
    CP_WAIT(0);
    __syncthreads();
}

// ---------------- fused tile kernel (+ per-strip pass2 + finalize) ----------------
__global__ __launch_bounds__(256, 2) void tile_kernel(float* out) {
    extern __shared__ char smem[];
    uint32_t su = (smem_u32(smem) + 127u) & ~127u;   // 128B align for XOR addressing
    const int tid = threadIdx.x, lane = tid & 31, wid = tid >> 5;
    const int wy = wid & 3, wx = wid >> 2;       // 4 row-groups x 2 col-groups
    const int ti = blockIdx.y * BM, tj = blockIdx.x * BN;
    const int q = lane & 3, g = lane >> 2;

    float acc[2][8][4];
#pragma unroll
    for (int a = 0; a < 2; a++)
#pragma unroll
        for (int b = 0; b < 8; b++)
#pragma unroll
            for (int c = 0; c < 4; c++) acc[a][b][c] = 0.f;

    // ---- gram = lab @ lab^T (K=256) ----
    gemm<NC>(g_labh, g_labh, ti, tj, su, tid, lane, wy, wx, acc);

    unsigned negbits[4];   // per local row rr: own 16 col bits (nt*2+j)
#pragma unroll
    for (int rr = 0; rr < 4; rr++) {
        const int mt = rr >> 1, hf = rr & 1;
        const int grow = ti + wy * 32 + mt * 16 + hf * 8 + g;
        unsigned pw0 = 0, pw1 = 0, nw0 = 0, nw1 = 0, own = 0;
#pragma unroll
        for (int nt = 0; nt < 8; nt++) {
#pragma unroll
            for (int j = 0; j < 2; j++) {
                float v = acc[mt][nt][hf * 2 + j];
                int col = nt * 8 + q * 2 + j;           // 0..63 within warp cols
                int gj = tj + wx * 64 + col;
                bool dg = (grow == gj);
                bool pos = (v > THRESH) && !dg;
                bool neg = !pos && !dg;
                unsigned bit = 1u << (col & 31);
                if (col < 32) { if (pos) pw0 |= bit; if (neg) nw0 |= bit; }
                else          { if (pos) pw1 |= bit; if (neg) nw1 |= bit; }
                if (neg) own |= 1u << (nt * 2 + j);
            }
        }
        negbits[rr] = own;
        pw0 |= __shfl_xor_sync(~0u, pw0, 1); pw0 |= __shfl_xor_sync(~0u, pw0, 2);
        pw1 |= __shfl_xor_sync(~0u, pw1, 1); pw1 |= __shfl_xor_sync(~0u, pw1, 2);
        nw0 |= __shfl_xor_sync(~0u, nw0, 1); nw0 |= __shfl_xor_sync(~0u, nw0, 2);
        nw1 |= __shfl_xor_sync(~0u, nw1, 1); nw1 |= __shfl_xor_sync(~0u, nw1, 2);
        if (q == 0) {
            size_t base = (size_t)grow * NWORD + (size_t)((tj + wx * 64) >> 5);
            g_posbits[base] = pw0;
            g_posbits[base + 1] = pw1;
            unsigned fl = ((pw0 | pw1) ? 1u : 0u) | ((nw0 | nw1) ? 2u : 0u);
            if (fl) atomicOr(&g_rowflags[grow], fl);
        }
    }

    // ---- sim = img @ txt^T (K=1024) ----
#pragma unroll
    for (int a = 0; a < 2; a++)
#pragma unroll
        for (int b = 0; b < 8; b++)
#pragma unroll
            for (int c = 0; c < 4; c++) acc[a][b][c] = 0.f;
    gemm<ND>(g_imgh, g_txth, ti, tj, su, tid, lane, wy, wx, acc);

#pragma unroll
    for (int rr = 0; rr < 4; rr++) {
        const int mt = rr >> 1, hf = rr & 1;
        const int grow = ti + wy * 32 + mt * 16 + hf * 8 + g;
        const unsigned own = negbits[rr];
        float mx = __int_as_float(0xff800000);   // -inf
        __nv_bfloat162* dst = reinterpret_cast<__nv_bfloat162*>(
            g_sim + (size_t)grow * NB + tj + wx * 64 + q * 2);
#pragma unroll
        for (int nt = 0; nt < 8; nt++) {
            float v0 = acc[mt][nt][hf * 2], v1 = acc[mt][nt][hf * 2 + 1];
            dst[nt * 4] = __floats2bfloat162_rn(v0, v1);
            if (own & (1u << (nt * 2)))     mx = fmaxf(mx, v0);
            if (own & (1u << (nt * 2 + 1))) mx = fmaxf(mx, v1);
        }
        mx = fmaxf(mx, __shfl_xor_sync(~0u, mx, 1));
        mx = fmaxf(mx, __shfl_xor_sync(~0u, mx, 2));
        if (q == 0) atomicMax(&g_rowmax[grow], encf(mx));
    }

    // ---- strip ticket: last CTA of this row strip does pass2 for its 128 rows ----
    __shared__ unsigned s_ticket;
    __shared__ double   ssum[8];
    __shared__ unsigned scnt[8];
    __threadfence();                       // publish sim/posbits/rowmax/rowflags
    __syncthreads();
    if (tid == 0) s_ticket = atomicAdd(&g_rowdone[blockIdx.y], 1u);
    __syncthreads();
    if (s_ticket != gridDim.x - 1) return;

    // pass2 over rows [ti, ti+BM): 32768 mask words, sim hot in L2
    float fs = 0.f;
    unsigned lcnt = 0u;
#pragma unroll 1
    for (int w = tid; w < BM * NWORD; w += 256) {
        int i  = ti + (w >> 8);            // NWORD = 256 words per row
        int jb = (w & 255) << 5;
        if (g_rowflags[i] == 3u) {         // valid = has_pos & has_neg
            unsigned m = g_posbits[(size_t)i * NWORD + (w & 255)];
            if (m) {
                lcnt += (unsigned)__popc(m);
                float base = MARGIN + decf(g_rowmax[i]);
                const uint4* rp = reinterpret_cast<const uint4*>(g_sim + (size_t)i * NB + jb);
                union { uint4 v[4]; unsigned u[16]; } row;
                row.v[0] = rp[0]; row.v[1] = rp[1]; row.v[2] = rp[2]; row.v[3] = rp[3];
#pragma unroll
                for (int k = 0; k < 16; k++) {
                    float2 f = __bfloat1622float2(
                        *reinterpret_cast<__nv_bfloat162*>(&row.u[k]));
                    if (m & (1u << (2 * k)))     { float h = base - f.x; if (h > 0.f) fs += h; }
                    if (m & (1u << (2 * k + 1))) { float h = base - f.y; if (h > 0.f) fs += h; }
                }
            }
        }
    }
    double lsum = (double)fs;
#pragma unroll
    for (int off = 16; off; off >>= 1) {
        lsum += __shfl_down_sync(0xffffffffu, lsum, off);
        lcnt += __shfl_down_sync(0xffffffffu, lcnt, off);
    }
    if (lane == 0) { ssum[wid] = lsum; scnt[wid] = lcnt; }
    __syncthreads();
    if (wid == 0) {
        lsum = (lane < 8) ? ssum[lane] : 0.0;
        lcnt = (lane < 8) ? scnt[lane] : 0u;
#pragma unroll
        for (int off = 4; off; off >>= 1) {
            lsum += __shfl_down_sync(0xffffffffu, lsum, off);
            lcnt += __shfl_down_sync(0xffffffffu, lcnt, off);
        }
        if (lane == 0) {
            atomicAdd(&g_sum, lsum);
            atomicAdd(&g_cnt, lcnt);
            __threadfence();
            unsigned t = atomicAdd(&g_done, 1u);
            if (t == NSTRIP - 1) {         // last strip finalizes
                double s = g_sum;
                unsigned c = g_cnt;
                out[0] = (c > 0u) ? (float)(s / (double)c) : 0.f;
            }
        }
    }
}

// ---------------- fused fp32 -> bf16 conversion (all 3 tensors) ----------------
#define NI (NB * ND / 8)   // 1048576 chunks of 8 floats
#define NL (NB * NC / 8)   // 262144
__global__ void cvt_all_kernel(const float* __restrict__ img,
                               const float* __restrict__ txt,
                               const float* __restrict__ lab) {
    int i = blockIdx.x * 256 + threadIdx.x;
    const float* src;
    __nv_bfloat16* dst;
    int off;
    if (i < NI)            { src = img; dst = g_imgh; off = i; }
    else if (i < 2 * NI)   { src = txt; dst = g_txth; off = i - NI; }
    else                   { src = lab; dst = g_labh; off = i - 2 * NI;
                             if (off >= NL) return; }
    float4 a = reinterpret_cast<const float4*>(src)[2 * off];
    float4 b = reinterpret_cast<const float4*>(src)[2 * off + 1];
    union { uint4 v; __nv_bfloat162 h[4]; } pk;
    pk.h[0] = __floats2bfloat162_rn(a.x, a.y);
    pk.h[1] = __floats2bfloat162_rn(a.z, a.w);
    pk.h[2] = __floats2bfloat162_rn(b.x, b.y);
    pk.h[3] = __floats2bfloat162_rn(b.z, b.w);
    reinterpret_cast<uint4*>(dst)[off] = pk.v;
}

// ---------------- resets ----------------
__global__ void reset_rows_kernel() {
    int i = blockIdx.x * 256 + threadIdx.x;
    if (i < NB) { g_rowmax[i] = 0x007fffffu; g_rowflags[i] = 0u; }   // encf(-inf)
}
__global__ void reset_scalars_kernel() {
    int i = threadIdx.x;
    if (i < NSTRIP) g_rowdone[i] = 0u;
    if (i == 0) { g_sum = 0.0; g_cnt = 0u; g_done = 0u; }
}

// ---------------- launch ----------------
extern "C" void kernel_launch(void* const* d_in, const int* in_sizes, int n_in,
                              void* d_out, int out_size) {
    const float* img = (const float*)d_in[0];
    const float* txt = (const float*)d_in[1];
    const float* lab = (const float*)d_in[2];
    (void)in_sizes; (void)n_in; (void)out_size;

    static int smem_set = 0;
    if (!smem_set) {
        cudaFuncSetAttribute(tile_kernel, cudaFuncAttributeMaxDynamicSharedMemorySize,
                             STAGES * STAGE_BYTES + 128);
        smem_set = 1;
    }

    dim3 grid(NB / BN, NB / BM);   // 64 x 64

    reset_rows_kernel<<<32, 256>>>();                                   // idx 0
    reset_scalars_kernel<<<1, 64>>>();                                  // idx 1
    cvt_all_kernel<<<(2 * NI + NL + 255) / 256, 256>>>(img, txt, lab);  // idx 2
    tile_kernel<<<grid, 256, STAGES * STAGE_BYTES + 128>>>((float*)d_out);  // idx 3 (profiled)
}

// round 12
// speedup vs baseline: 1.2797x; 1.2797x over previous
#include <cuda_runtime.h>
#include <cuda_bf16.h>
#include <cstdint>

#define NB 8192
#define ND 1024
#define NC 256
#define MARGIN 0.2f
#define THRESH 0.5f
#define NWORD (NB / 32)

#define BM 128
#define BN 128
#define BK 64
#define STAGES 3
#define STAGE_BYTES 32768          // A tile 16 KB + B tile 16 KB
#define B_OFF 16384
#define PM_STRIDE 132              // pos-byte matrix row stride (pad vs bank conflicts)
#define SWZ(o) ((o) ^ (((o) >> 3) & 0x70))   // SW128 swizzle

// ---------------- device scratch ----------------
__device__ __align__(16) __nv_bfloat16 g_imgh[(size_t)NB * ND];
__device__ __align__(16) __nv_bfloat16 g_txth[(size_t)NB * ND];
__device__ __align__(16) __nv_bfloat16 g_labh[(size_t)NB * NC];
__device__ __align__(16) __nv_bfloat16 g_sim[(size_t)NB * NB];   // 128 MB
__device__ unsigned g_posbits[(size_t)NB * NWORD];               // fully overwritten each run
__device__ unsigned g_rowmax[NB];
__device__ unsigned g_rowflags[NB];
__device__ double   g_sum;
__device__ unsigned g_cnt;
__device__ unsigned g_done;

// monotone encode/decode: unsigned atomicMax == float max
__device__ __forceinline__ unsigned encf(float f) {
    unsigned u = __float_as_uint(f);
    return (u & 0x80000000u) ? ~u : (u | 0x80000000u);
}
__device__ __forceinline__ float decf(unsigned u) {
    u = (u & 0x80000000u) ? (u & 0x7fffffffu) : ~u;
    return __uint_as_float(u);
}
__device__ __forceinline__ uint32_t smem_u32(const void* p) {
    uint32_t a;
    asm("{ .reg .u64 t; cvta.to.shared.u64 t, %1; cvt.u32.u64 %0, t; }" : "=r"(a) : "l"(p));
    return a;
}
__device__ __forceinline__ void cp16(uint32_t dst, const void* src) {
    asm volatile("cp.async.cg.shared.global [%0], [%1], 16;" :: "r"(dst), "l"(src));
}
#define CP_COMMIT() asm volatile("cp.async.commit_group;" ::: "memory")
#define CP_WAIT(n)  asm volatile("cp.async.wait_group %0;" :: "n"(n) : "memory")

__device__ __forceinline__ void ldsm4(uint32_t addr, uint32_t r[4]) {
    asm volatile("ldmatrix.sync.aligned.m8n8.x4.shared.b16 {%0,%1,%2,%3}, [%4];"
                 : "=r"(r[0]), "=r"(r[1]), "=r"(r[2]), "=r"(r[3]) : "r"(addr));
}
__device__ __forceinline__ void mma16816(float d[4], const uint32_t a[4],
                                         uint32_t b0, uint32_t b1) {
    asm volatile("mma.sync.aligned.m16n8k16.row.col.f32.bf16.bf16.f32 "
                 "{%0,%1,%2,%3}, {%4,%5,%6,%7}, {%8,%9}, {%0,%1,%2,%3};"
                 : "+f"(d[0]), "+f"(d[1]), "+f"(d[2]), "+f"(d[3])
                 : "r"(a[0]), "r"(a[1]), "r"(a[2]), "r"(a[3]), "r"(b0), "r"(b1));
}

// ---------------- stage load: A[128x64] + B[128x64] bf16, SW128 swizzled ----------------
__device__ __forceinline__ void load_stage(const __nv_bfloat16* __restrict__ Ag,
                                           const __nv_bfloat16* __restrict__ Bg,
                                           int K, int ti, int tj, int k0,
                                           uint32_t sbase, int tid) {
#pragma unroll
    for (int u = 0; u < 4; u++) {
        int ch = u * 256 + tid, row = ch >> 3, cc = ch & 7;
        cp16(sbase + SWZ((uint32_t)(row * 128 + cc * 16)),
             (const char*)(Ag + (size_t)(ti + row) * K + k0) + cc * 16);
    }
#pragma unroll
    for (int u = 0; u < 4; u++) {
        int ch = u * 256 + tid, row = ch >> 3, cc = ch & 7;
        cp16(sbase + B_OFF + SWZ((uint32_t)(row * 128 + cc * 16)),
             (const char*)(Bg + (size_t)(tj + row) * K + k0) + cc * 16);
    }
}

// ---------------- compute one 64-wide K stage: warp tile 32x64, 2x8 mma grid ----------
// Fragment double-buffered; per-kk ldsm address = base ^ (kk*32) (SW128 row-only XOR).
__device__ __forceinline__ void compute_stage(uint32_t sA, uint32_t sB, int lane,
                                              int wy, int wx, float acc[2][8][4]) {
    uint32_t aB[2], bB[4];
#pragma unroll
    for (int mt = 0; mt < 2; mt++) {
        uint32_t row = wy * 32 + mt * 16 + (lane & 15);
        uint32_t t   = (row & 7) * 16;
        uint32_t sel = (lane >> 4) * 16;
        aB[mt] = sA + row * 128 + (sel ^ t);
    }
#pragma unroll
    for (int p = 0; p < 4; p++) {
        uint32_t n   = wx * 64 + p * 16 + (lane >> 4) * 8 + (lane & 7);
        uint32_t t   = (n & 7) * 16;
        uint32_t sel = ((lane >> 3) & 1) * 16;
        bB[p] = sB + n * 128 + (sel ^ t);
    }

    uint32_t af[2][2][4], bf[2][4][4];
    ldsm4(aB[0], af[0][0]); ldsm4(aB[1], af[0][1]);
    ldsm4(bB[0], bf[0][0]); ldsm4(bB[1], bf[0][1]);
    ldsm4(bB[2], bf[0][2]); ldsm4(bB[3], bf[0][3]);

#pragma unroll
    for (int kk = 0; kk < 4; kk++) {
        const int cur = kk & 1, nxt = cur ^ 1;
        if (kk < 3) {
            uint32_t kx = (uint32_t)(kk + 1) * 32;
            ldsm4(aB[0] ^ kx, af[nxt][0]); ldsm4(aB[1] ^ kx, af[nxt][1]);
            ldsm4(bB[0] ^ kx, bf[nxt][0]); ldsm4(bB[1] ^ kx, bf[nxt][1]);
            ldsm4(bB[2] ^ kx, bf[nxt][2]); ldsm4(bB[3] ^ kx, bf[nxt][3]);
        }
#pragma unroll
        for (int mt = 0; mt < 2; mt++)
#pragma unroll
            for (int p = 0; p < 4; p++) {
                mma16816(acc[mt][2 * p],     af[cur][mt], bf[cur][p][0], bf[cur][p][1]);
                mma16816(acc[mt][2 * p + 1], af[cur][mt], bf[cur][p][2], bf[cur][p][3]);
            }
    }
}

// ---------------- pipelined GEMM: acc += A[ti:,:] @ B[tj:,:]^T over K ----------------
template <int K>
__device__ __forceinline__ void gemm(const __nv_bfloat16* __restrict__ Ag,
                                     const __nv_bfloat16* __restrict__ Bg,
                                     int ti, int tj, uint32_t su,
                                     int tid, int lane, int wy, int wx,
                                     float acc[2][8][4]) {
    constexpr int NS = K / BK;
#pragma unroll
    for (int s = 0; s < STAGES - 1; s++) {
        load_stage(Ag, Bg, K, ti, tj, s * BK, su + s * STAGE_BYTES, tid);
        CP_COMMIT();
    }
#pragma unroll 1
    for (int ks = 0; ks < NS; ks++) {
        CP_WAIT(STAGES - 2);
        __syncthreads();
        int nx = ks + STAGES - 1;
        if (nx < NS)
            load_stage(Ag, Bg, K, ti, tj, nx * BK, su + (nx % STAGES) * STAGE_BYTES, tid);
        CP_COMMIT();
        uint32_t sb = su + (ks % STAGES) * STAGE_BYTES;
        compute_stage(sb, sb + B_OFF, lane, wy, wx, acc);
    }
    CP_WAIT(0);
    __syncthreads();
}

// ---------------- gram kernel: upper-triangle tiles only, writes both (i,j) and (j,i) ----
__global__ __launch_bounds__(256, 2) void gram_kernel() {
    const int bx = blockIdx.x, by = blockIdx.y;
    if (bx < by) return;                         // upper triangle (bx >= by)
    extern __shared__ char smem[];
    uint32_t su = (smem_u32(smem) + 127u) & ~127u;
    unsigned char* pm = (unsigned char*)smem;    // reuse pipeline smem after GEMM
    const int tid = threadIdx.x, lane = tid & 31, wid = tid >> 5;
    const int wy = wid & 3, wx = wid >> 2;
    const int ti = by * BM, tj = bx * BN;
    const int q = lane & 3, g = lane >> 2;

    float acc[2][8][4];
#pragma unroll
    for (int a = 0; a < 2; a++)
#pragma unroll
        for (int b = 0; b < 8; b++)
#pragma unroll
            for (int c = 0; c < 4; c++) acc[a][b][c] = 0.f;

    gemm<NC>(g_labh, g_labh, ti, tj, su, tid, lane, wy, wx, acc);
    // gemm ends with CP_WAIT(0)+__syncthreads -> smem free for pm

    // write pos/neg/diag bytes: 1=pos, 0=neg, 2=diag
#pragma unroll
    for (int mt = 0; mt < 2; mt++)
#pragma unroll
        for (int hf = 0; hf < 2; hf++) {
            const int lr = wy * 32 + mt * 16 + hf * 8 + g;     // local row
            const int grow = ti + lr;
#pragma unroll
            for (int nt = 0; nt < 8; nt++)
#pragma unroll
                for (int j = 0; j < 2; j++) {
                    const int lc = wx * 64 + nt * 8 + q * 2 + j;   // local col
                    const int gj = tj + lc;
                    float v = acc[mt][nt][hf * 2 + j];
                    unsigned char b = (grow == gj) ? 2 : (v > THRESH ? 1 : 0);
                    pm[lr * PM_STRIDE + lc] = b;
                }
        }
    __syncthreads();

    // pack bits for i-block rows (cols tj..tj+127)
#pragma unroll 1
    for (int t = tid; t < 512; t += 256) {
        int row = t >> 2, w = t & 3;
        unsigned posw = 0u; bool negany = false;
        const unsigned char* pr = pm + row * PM_STRIDE + w * 32;
#pragma unroll
        for (int b = 0; b < 32; b++) {
            unsigned char v = pr[b];
            posw |= (unsigned)(v == 1) << b;
            negany |= (v == 0);
        }
        g_posbits[(size_t)(ti + row) * NWORD + (tj >> 5) + w] = posw;
        unsigned fl = (posw ? 1u : 0u) | (negany ? 2u : 0u);
        if (fl) atomicOr(&g_rowflags[ti + row], fl);
    }

    // transposed: j-block rows (cols ti..ti+127); skip on diagonal tiles (same words)
    if (bx > by) {
#pragma unroll 1
        for (int t = tid; t < 512; t += 256) {
            int row = t >> 2, w = t & 3;       // row = local col c in j-block
            unsigned posw = 0u; bool negany = false;
            const unsigned char* pc = pm + row + (w * 32) * PM_STRIDE;
#pragma unroll
            for (int b = 0; b < 32; b++) {
                unsigned char v = pc[(size_t)b * PM_STRIDE];
                posw |= (unsigned)(v == 1) << b;
                negany |= (v == 0);
            }
            g_posbits[(size_t)(tj + row) * NWORD + (ti >> 5) + w] = posw;
            unsigned fl = (posw ? 1u : 0u) | (negany ? 2u : 0u);
            if (fl) atomicOr(&g_rowflags[tj + row], fl);
        }
    }
}

// ---------------- sim kernel: bf16 sim store + row max over negatives ----------------
__global__ __launch_bounds__(256, 2) void sim_kernel() {
    extern __shared__ char smem[];
    uint32_t su = (smem_u32(smem) + 127u) & ~127u;
    const int tid = threadIdx.x, lane = tid & 31, wid = tid >> 5;
    const int wy = wid & 3, wx = wid >> 2;
    const int ti = blockIdx.y * BM, tj = blockIdx.x * BN;
    const int q = lane & 3, g = lane >> 2;

    float acc[2][8][4];
#pragma unroll
    for (int a = 0; a < 2; a++)
#pragma unroll
        for (int b = 0; b < 8; b++)
#pragma unroll
            for (int c = 0; c < 4; c++) acc[a][b][c] = 0.f;

    gemm<ND>(g_imgh, g_txth, ti, tj, su, tid, lane, wy, wx, acc);

#pragma unroll
    for (int rr = 0; rr < 4; rr++) {
        const int mt = rr >> 1, hf = rr & 1;
        const int grow = ti + wy * 32 + mt * 16 + hf * 8 + g;
        size_t base = (size_t)grow * NWORD + (size_t)((tj + wx * 64) >> 5);
        const unsigned pw0 = g_posbits[base], pw1 = g_posbits[base + 1];
        float mx = __int_as_float(0xff800000);   // -inf
        __nv_bfloat162* dst = reinterpret_cast<__nv_bfloat162*>(
            g_sim + (size_t)grow * NB + tj + wx * 64 + q * 2);
#pragma unroll
        for (int nt = 0; nt < 8; nt++) {
            float v0 = acc[mt][nt][hf * 2], v1 = acc[mt][nt][hf * 2 + 1];
            dst[nt * 4] = __floats2bfloat162_rn(v0, v1);
#pragma unroll
            for (int j = 0; j < 2; j++) {
                float v = j ? v1 : v0;
                int col = nt * 8 + q * 2 + j;
                int gj = tj + wx * 64 + col;
                unsigned pw = (col < 32) ? pw0 : pw1;
                bool pos = (pw >> (col & 31)) & 1u;
                if (!pos && gj != grow) mx = fmaxf(mx, v);
            }
        }
        mx = fmaxf(mx, __shfl_xor_sync(~0u, mx, 1));
        mx = fmaxf(mx, __shfl_xor_sync(~0u, mx, 2));
        if (q == 0) atomicMax(&g_rowmax[grow], encf(mx));
    }
}

// ---------------- fused fp32 -> bf16 conversion (all 3 tensors) ----------------
#define NI (NB * ND / 8)   // 1048576 chunks of 8 floats
#define NL (NB * NC / 8)   // 262144
__global__ void cvt_all_kernel(const float* __restrict__ img,
                               const float* __restrict__ txt,
                               const float* __restrict__ lab) {
    int i = blockIdx.x * 256 + threadIdx.x;
    const float* src;
    __nv_bfloat16* dst;
    int off;
    if (i < NI)            { src = img; dst = g_imgh; off = i; }
    else if (i < 2 * NI)   { src = txt; dst = g_txth; off = i - NI; }
    else                   { src = lab; dst = g_labh; off = i - 2 * NI;
                             if (off >= NL) return; }
    float4 a = reinterpret_cast<const float4*>(src)[2 * off];
    float4 b = reinterpret_cast<const float4*>(src)[2 * off + 1];
    union { uint4 v; __nv_bfloat162 h[4]; } pk;
    pk.h[0] = __floats2bfloat162_rn(a.x, a.y);
    pk.h[1] = __floats2bfloat162_rn(a.z, a.w);
    pk.h[2] = __floats2bfloat162_rn(b.x, b.y);
    pk.h[3] = __floats2bfloat162_rn(b.z, b.w);
    reinterpret_cast<uint4*>(dst)[off] = pk.v;
}

// ---------------- reset ----------------
__global__ void reset_kernel() {
    int i = blockIdx.x * 256 + threadIdx.x;
    if (i < NB) { g_rowmax[i] = 0x007fffffu; g_rowflags[i] = 0u; }   // encf(-inf)
    if (i == 0) { g_sum = 0.0; g_cnt = 0u; g_done = 0u; }
}

// ---------------- pass 2 + finalize: hinge sum over positive pairs ----------------
__global__ void pass2_kernel(float* out) {
    int w = blockIdx.x * 256 + threadIdx.x;   // one 32-col mask word per thread
    float fs = 0.f;
    unsigned lcnt = 0u;
    int i  = w >> 8;
    int jb = (w & 255) << 5;
    if (g_rowflags[i] == 3u) {                // valid = has_pos & has_neg
        unsigned m = g_posbits[w];
        if (m) {
            lcnt = (unsigned)__popc(m);
            float base = MARGIN + decf(g_rowmax[i]);
            const uint4* rp = reinterpret_cast<const uint4*>(g_sim + (size_t)i * NB + jb);
            union { uint4 v[4]; unsigned u[16]; } row;
            row.v[0] = rp[0]; row.v[1] = rp[1]; row.v[2] = rp[2]; row.v[3] = rp[3];
#pragma unroll
            for (int k = 0; k < 16; k++) {
                float2 f = __bfloat1622float2(
                    *reinterpret_cast<__nv_bfloat162*>(&row.u[k]));
                if (m & (1u << (2 * k)))     { float h = base - f.x; if (h > 0.f) fs += h; }
                if (m & (1u << (2 * k + 1))) { float h = base - f.y; if (h > 0.f) fs += h; }
            }
        }
    }
    double lsum = (double)fs;
#pragma unroll
    for (int off = 16; off; off >>= 1) {
        lsum += __shfl_down_sync(0xffffffffu, lsum, off);
        lcnt += __shfl_down_sync(0xffffffffu, lcnt, off);
    }
    __shared__ double ssum[8];
    __shared__ unsigned scnt[8];
    int lane = threadIdx.x & 31, wid = threadIdx.x >> 5;
    if (lane == 0) { ssum[wid] = lsum; scnt[wid] = lcnt; }
    __syncthreads();
    if (wid == 0) {
        lsum = (lane < 8) ? ssum[lane] : 0.0;
        lcnt = (lane < 8) ? scnt[lane] : 0u;
#pragma unroll
        for (int off = 4; off; off >>= 1) {
            lsum += __shfl_down_sync(0xffffffffu, lsum, off);
            lcnt += __shfl_down_sync(0xffffffffu, lcnt, off);
        }
        if (lane == 0) {
            atomicAdd(&g_sum, lsum);
            atomicAdd(&g_cnt, lcnt);
            __threadfence();
            unsigned t = atomicAdd(&g_done, 1u);
            if (t == gridDim.x - 1) {        // last block finalizes
                double s = g_sum;
                unsigned c = g_cnt;
                out[0] = (c > 0u) ? (float)(s / (double)c) : 0.f;
            }
        }
    }
}

// ---------------- launch ----------------
extern "C" void kernel_launch(void* const* d_in, const int* in_sizes, int n_in,
                              void* d_out, int out_size) {
    const float* img = (const float*)d_in[0];
    const float* txt = (const float*)d_in[1];
    const float* lab = (const float*)d_in[2];
    (void)in_sizes; (void)n_in; (void)out_size;

    static int smem_set = 0;
    if (!smem_set) {
        cudaFuncSetAttribute(gram_kernel, cudaFuncAttributeMaxDynamicSharedMemorySize,
                             STAGES * STAGE_BYTES + 128);
        cudaFuncSetAttribute(sim_kernel, cudaFuncAttributeMaxDynamicSharedMemorySize,
                             STAGES * STAGE_BYTES + 128);
        smem_set = 1;
    }

    dim3 grid(NB / BN, NB / BM);   // 64 x 64

    reset_kernel<<<32, 256>>>();                                        // idx 0
    cvt_all_kernel<<<(2 * NI + NL + 255) / 256, 256>>>(img, txt, lab);  // idx 1
    gram_kernel<<<grid, 256, STAGES * STAGE_BYTES + 128>>>();           // idx 2
    sim_kernel<<<grid, 256, STAGES * STAGE_BYTES + 128>>>();            // idx 3 (profiled)
    pass2_kernel<<<NB * NWORD / 256, 256>>>((float*)d_out);             // idx 4
}